// round 3
// baseline (speedup 1.0000x reference)
#include <cuda_runtime.h>

#define DD 128
#define MAXN 100000

// Scratch (no allocations allowed) --------------------------------------------
__device__ __align__(16) float g_A[(size_t)MAXN * DD];   // (1+eps)*x + aggr
__device__ __align__(16) float g_Y[(size_t)MAXN * DD];   // GEMM output (in-place layer 2)
// layout: [0:128) sum1 [128:256) sq1 [256:384) sum2 [384:512) sq2
//         [512:640) s1 [640:768) t1 [768:896) s2 [896:1024) t2
__device__ float g_stat[8 * DD];
__device__ int   g_i64flag;

// ---------------------------------------------------------------------------
// Probe edge-index dtype: int64 little-endian (values < 2^31) => all odd 32-bit
// words of the first 2E words are zero. int32 => they are random node ids.
__global__ void k_detect(const int* __restrict__ w, int E) {
    __shared__ int s_or;
    if (threadIdx.x == 0) s_or = 0;
    __syncthreads();
    int total = 2 * E;
    int step = total / 4096; if (step < 2) step = 2;
    int acc = 0;
    for (int i = threadIdx.x; i < 4096; i += blockDim.x) {
        long long idx = ((long long)i * step) | 1;   // odd word
        if (idx < total) acc |= w[idx];
    }
    atomicOr(&s_or, acc);
    __syncthreads();
    if (threadIdx.x == 0) g_i64flag = (s_or == 0) ? 1 : 0;
}

// ---------------------------------------------------------------------------
// A = (1+eps) * x ; also zero ALL 512 stat accumulators (256 threads x 2)
__global__ void k_init(const float4* __restrict__ x, const float* __restrict__ eps, int n4) {
    if (blockIdx.x == 0 && threadIdx.x < 256) {
        g_stat[threadIdx.x] = 0.0f;
        g_stat[threadIdx.x + 256] = 0.0f;
    }
    float e = 1.0f + __ldg(eps);
    float4* A4 = reinterpret_cast<float4*>(g_A);
    for (int i = blockIdx.x * blockDim.x + threadIdx.x; i < n4; i += gridDim.x * blockDim.x) {
        float4 v = __ldg(&x[i]);
        v.x *= e; v.y *= e; v.z *= e; v.w *= e;
        A4[i] = v;
    }
}

// ---------------------------------------------------------------------------
// One warp per edge: gather 512B source row, vector-RED into destination row.
__global__ void k_scatter(const float4* __restrict__ x, const int* __restrict__ w, int E) {
    int gw = (blockIdx.x * blockDim.x + threadIdx.x) >> 5;
    int lane = threadIdx.x & 31;
    if (gw >= E) return;
    int s, d;
    if (g_i64flag) {                 // int64 buffer viewed as int32 words
        s = __ldg(&w[2 * gw]);
        d = __ldg(&w[2 * (E + gw)]);
    } else {                         // genuine int32
        s = __ldg(&w[gw]);
        d = __ldg(&w[E + gw]);
    }
    float4 v = __ldg(&x[(size_t)s * 32 + lane]);
    float* p = g_A + (size_t)d * DD + lane * 4;
    asm volatile("red.global.add.v4.f32 [%0], {%1,%2,%3,%4};"
                 :: "l"(p), "f"(v.x), "f"(v.y), "f"(v.z), "f"(v.w) : "memory");
}

// ---------------------------------------------------------------------------
// C[i,j] = sum_k A'[i,k] * W[j,k] + b[j], A' = A (layer1) or relu(Y*s1+t1) (layer2).
// Fused epilogue: column sum / sum-of-squares accumulation for BatchNorm.
template <int LAYER>
__global__ __launch_bounds__(256) void k_gemm(const float* __restrict__ W,
                                              const float* __restrict__ bias, int N) {
    __shared__ float As[16][DD + 4];
    __shared__ float Ws[16][DD + 4];
    __shared__ float sS[DD], sT[DD];

    const float* A = (LAYER == 1) ? g_A : g_Y;
    float* C = g_Y;
    float* osum = g_stat + (LAYER == 1 ? 0 : 2 * DD);
    float* osq  = osum + DD;

    int tid = threadIdx.x;
    if (LAYER == 2 && tid < DD) {
        sS[tid] = g_stat[4 * DD + tid];
        sT[tid] = g_stat[5 * DD + tid];
    }
    __syncthreads();

    int row0 = blockIdx.x * 128;
    int tx = tid & 15, ty = tid >> 4;
    int lr0 = tid >> 2;          // 0..63
    int lc  = (tid & 3) * 4;     // 0,4,8,12

    float acc[8][8];
#pragma unroll
    for (int m = 0; m < 8; m++)
#pragma unroll
        for (int n = 0; n < 8; n++) acc[m][n] = 0.0f;

#pragma unroll 1
    for (int kb = 0; kb < 8; kb++) {
        int k0 = kb * 16;
#pragma unroll
        for (int h = 0; h < 2; h++) {
            int r = lr0 + h * 64;
            int grow = row0 + r;
            float4 v = make_float4(0.f, 0.f, 0.f, 0.f);
            if (grow < N)
                v = *reinterpret_cast<const float4*>(&A[(size_t)grow * DD + k0 + lc]);
            if (LAYER == 2) {
                v.x = fmaxf(fmaf(v.x, sS[k0 + lc + 0], sT[k0 + lc + 0]), 0.f);
                v.y = fmaxf(fmaf(v.y, sS[k0 + lc + 1], sT[k0 + lc + 1]), 0.f);
                v.z = fmaxf(fmaf(v.z, sS[k0 + lc + 2], sT[k0 + lc + 2]), 0.f);
                v.w = fmaxf(fmaf(v.w, sS[k0 + lc + 3], sT[k0 + lc + 3]), 0.f);
            }
            As[lc + 0][r] = v.x; As[lc + 1][r] = v.y;
            As[lc + 2][r] = v.z; As[lc + 3][r] = v.w;
        }
#pragma unroll
        for (int h = 0; h < 2; h++) {
            int col = lr0 + h * 64;
            float4 w = *reinterpret_cast<const float4*>(&W[(size_t)col * DD + k0 + lc]);
            Ws[lc + 0][col] = w.x; Ws[lc + 1][col] = w.y;
            Ws[lc + 2][col] = w.z; Ws[lc + 3][col] = w.w;
        }
        __syncthreads();
#pragma unroll
        for (int k = 0; k < 16; k++) {
            float ra[8], rb[8];
#pragma unroll
            for (int m = 0; m < 8; m++) ra[m] = As[k][ty * 8 + m];
#pragma unroll
            for (int n = 0; n < 8; n++) rb[n] = Ws[k][tx * 8 + n];
#pragma unroll
            for (int m = 0; m < 8; m++)
#pragma unroll
                for (int n = 0; n < 8; n++) acc[m][n] = fmaf(ra[m], rb[n], acc[m][n]);
        }
        __syncthreads();
    }

    // Epilogue: bias, store, per-column stats
    float bb[8];
#pragma unroll
    for (int n = 0; n < 8; n++) bb[n] = __ldg(&bias[tx * 8 + n]);

    float psum[8], psq[8];
#pragma unroll
    for (int n = 0; n < 8; n++) { psum[n] = 0.f; psq[n] = 0.f; }

#pragma unroll
    for (int m = 0; m < 8; m++) {
        int row = row0 + ty * 8 + m;
        if (row < N) {
            float out[8];
#pragma unroll
            for (int n = 0; n < 8; n++) {
                out[n] = acc[m][n] + bb[n];
                psum[n] += out[n];
                psq[n]  = fmaf(out[n], out[n], psq[n]);
            }
            float4* dst = reinterpret_cast<float4*>(&C[(size_t)row * DD + tx * 8]);
            dst[0] = make_float4(out[0], out[1], out[2], out[3]);
            dst[1] = make_float4(out[4], out[5], out[6], out[7]);
        }
    }

    int lane = tid & 31;
#pragma unroll
    for (int n = 0; n < 8; n++) {
        float s = psum[n] + __shfl_xor_sync(0xffffffffu, psum[n], 16);
        float q = psq[n]  + __shfl_xor_sync(0xffffffffu, psq[n], 16);
        if (lane < 16) {  // lanes l and l+16 share tx (same columns)
            atomicAdd(&osum[tx * 8 + n], s);
            atomicAdd(&osq[tx * 8 + n],  q);
        }
    }
}

// ---------------------------------------------------------------------------
// BN params: scale = g*rsqrt(var+eps), shift = beta - mean*scale
template <int LAYER>
__global__ void k_bn(const float* __restrict__ g, const float* __restrict__ beta, int N) {
    int j = threadIdx.x;
    const float* sum = g_stat + (LAYER == 1 ? 0 : 2 * DD);
    float invN = 1.0f / (float)N;
    float mean = sum[j] * invN;
    float var  = sum[DD + j] * invN - mean * mean;
    float sc = __ldg(&g[j]) * rsqrtf(var + 1e-5f);
    float* outS = g_stat + (LAYER == 1 ? 4 * DD : 6 * DD);
    outS[j] = sc;
    outS[DD + j] = __ldg(&beta[j]) - mean * sc;
}

// ---------------------------------------------------------------------------
// out = relu(Y*s2 + t2)
__global__ void k_final(float* __restrict__ out, int n4) {
    const float4* Y4 = reinterpret_cast<const float4*>(g_Y);
    float4* o4 = reinterpret_cast<float4*>(out);
    for (int i = blockIdx.x * blockDim.x + threadIdx.x; i < n4; i += gridDim.x * blockDim.x) {
        int cb = (i & 31) * 4;
        float4 y = Y4[i];
        float4 r;
        r.x = fmaxf(fmaf(y.x, g_stat[6 * DD + cb + 0], g_stat[7 * DD + cb + 0]), 0.f);
        r.y = fmaxf(fmaf(y.y, g_stat[6 * DD + cb + 1], g_stat[7 * DD + cb + 1]), 0.f);
        r.z = fmaxf(fmaf(y.z, g_stat[6 * DD + cb + 2], g_stat[7 * DD + cb + 2]), 0.f);
        r.w = fmaxf(fmaf(y.w, g_stat[6 * DD + cb + 3], g_stat[7 * DD + cb + 3]), 0.f);
        o4[i] = r;
    }
}

// ---------------------------------------------------------------------------
extern "C" void kernel_launch(void* const* d_in, const int* in_sizes, int n_in,
                              void* d_out, int out_size) {
    const float* x   = (const float*)d_in[0];
    const int*   ei  = (const int*)d_in[1];
    const float* eps = (const float*)d_in[2];
    const float* W1  = (const float*)d_in[3];
    const float* b1  = (const float*)d_in[4];
    const float* g1  = (const float*)d_in[5];
    const float* be1 = (const float*)d_in[6];
    const float* W2  = (const float*)d_in[7];
    const float* b2  = (const float*)d_in[8];
    const float* g2  = (const float*)d_in[9];
    const float* be2 = (const float*)d_in[10];

    int N  = in_sizes[0] / DD;
    int E  = in_sizes[1] / 2;
    int n4 = N * (DD / 4);
    int gb = (N + 127) / 128;

    k_detect<<<1, 256>>>(ei, E);
    k_init<<<2048, 256>>>((const float4*)x, eps, n4);
    k_scatter<<<(E + 7) / 8, 256>>>((const float4*)x, ei, E);
    k_gemm<1><<<gb, 256>>>(W1, b1, N);
    k_bn<1><<<1, DD>>>(g1, be1, N);
    k_gemm<2><<<gb, 256>>>(W2, b2, N);
    k_bn<2><<<1, DD>>>(g2, be2, N);
    k_final<<<2048, 256>>>((float*)d_out, n4);
}

// round 6
// speedup vs baseline: 3.5250x; 3.5250x over previous
#include <cuda_runtime.h>
#include <cuda_bf16.h>
#include <cstdint>

#define DD 128
#define MAXN 100000
#define LDA 136                      // smem tile stride (bf16 elems), conflict-free ldmatrix

// ---- scratch (no allocs allowed) -------------------------------------------
__device__ __align__(16) float g_A[(size_t)MAXN * DD];   // (1+eps)x + aggr
__device__ __align__(16) float g_Y[(size_t)MAXN * DD];   // layer outputs (in-place L2)
// [0:128) sum1 [128:256) sq1 [256:384) sum2 [384:512) sq2
// [512:640) s1 [640:768) t1 [768:896) s2 [896:1024) t2
__device__ float g_stat[8 * DD];
__device__ int   g_i64flag;
__device__ __align__(16) __nv_bfloat16 g_Whi[2][DD * DD];
__device__ __align__(16) __nv_bfloat16 g_Wlo[2][DD * DD];

#define SMEMU32(p) ((uint32_t)__cvta_generic_to_shared(p))

__device__ __forceinline__ void ldx4(uint32_t* r, uint32_t addr) {
    asm volatile("ldmatrix.sync.aligned.m8n8.x4.shared.b16 {%0,%1,%2,%3}, [%4];"
                 : "=r"(r[0]), "=r"(r[1]), "=r"(r[2]), "=r"(r[3]) : "r"(addr));
}
__device__ __forceinline__ void mma16816(float* c, const uint32_t* a, uint32_t b0, uint32_t b1) {
    asm volatile("mma.sync.aligned.m16n8k16.row.col.f32.bf16.bf16.f32 "
                 "{%0,%1,%2,%3}, {%4,%5,%6,%7}, {%8,%9}, {%0,%1,%2,%3};"
                 : "+f"(c[0]), "+f"(c[1]), "+f"(c[2]), "+f"(c[3])
                 : "r"(a[0]), "r"(a[1]), "r"(a[2]), "r"(a[3]), "r"(b0), "r"(b1));
}

// ---------------------------------------------------------------------------
__global__ void k_detect(const int* __restrict__ w, int E) {
    __shared__ int s_or;
    if (threadIdx.x == 0) s_or = 0;
    __syncthreads();
    int total = 2 * E;
    int step = total / 4096; if (step < 2) step = 2;
    int acc = 0;
    for (int i = threadIdx.x; i < 4096; i += blockDim.x) {
        long long idx = ((long long)i * step) | 1;
        if (idx < total) acc |= w[idx];
    }
    atomicOr(&s_or, acc);
    __syncthreads();
    if (threadIdx.x == 0) g_i64flag = (s_or == 0) ? 1 : 0;
}

// ---------------------------------------------------------------------------
__global__ void k_init(const float4* __restrict__ x, const float* __restrict__ eps, int n4) {
    if (blockIdx.x == 0 && threadIdx.x < 256) {
        g_stat[threadIdx.x] = 0.0f;
        g_stat[threadIdx.x + 256] = 0.0f;
    }
    float e = 1.0f + __ldg(eps);
    float4* A4 = reinterpret_cast<float4*>(g_A);
    for (int i = blockIdx.x * blockDim.x + threadIdx.x; i < n4; i += gridDim.x * blockDim.x) {
        float4 v = __ldg(&x[i]);
        v.x *= e; v.y *= e; v.z *= e; v.w *= e;
        A4[i] = v;
    }
}

// ---------------------------------------------------------------------------
__global__ void k_prep(const float* __restrict__ W1, const float* __restrict__ W2) {
    int i = blockIdx.x * blockDim.x + threadIdx.x;
    if (i >= 2 * DD * DD) return;
    int layer = i >> 14, j = i & (DD * DD - 1);
    float v = (layer == 0) ? W1[j] : W2[j];
    __nv_bfloat16 h = __float2bfloat16_rn(v);
    g_Whi[layer][j] = h;
    g_Wlo[layer][j] = __float2bfloat16_rn(v - __bfloat162float(h));
}

// ---------------------------------------------------------------------------
__global__ void k_scatter(const float4* __restrict__ x, const int* __restrict__ w, int E) {
    int gw = (blockIdx.x * blockDim.x + threadIdx.x) >> 5;
    int lane = threadIdx.x & 31;
    if (gw >= E) return;
    int s, d;
    if (g_i64flag) { s = __ldg(&w[2 * gw]); d = __ldg(&w[2 * (E + gw)]); }
    else           { s = __ldg(&w[gw]);     d = __ldg(&w[E + gw]); }
    float4 v = __ldg(&x[(size_t)s * 32 + lane]);
    float* p = g_A + (size_t)d * DD + lane * 4;
    asm volatile("red.global.add.v4.f32 [%0], {%1,%2,%3,%4};"
                 :: "l"(p), "f"(v.x), "f"(v.y), "f"(v.z), "f"(v.w) : "memory");
}

// ---------------------------------------------------------------------------
// mma.sync GEMM: CTA = 128x128 tile, K=128. bf16 hi/lo x3 emulation.
// smem: A_hi @0, A_lo @34816, W_hi @69632, W_lo @104448 (128 x LDA bf16 each)
template <int LAYER>
__global__ __launch_bounds__(256) void k_gemm_tc(const float* __restrict__ bias, int Nn) {
    extern __shared__ char dynsm[];
    __shared__ float s_bias[DD];
    __shared__ float s_s[DD], s_t[DD];

    const uint32_t sbase = SMEMU32(dynsm);
    const uint32_t AHI = sbase, ALO = sbase + 34816, WHI = sbase + 69632, WLO = sbase + 104448;

    int tid = threadIdx.x, wid = tid >> 5, lane = tid & 31;
    if (tid < DD) {
        s_bias[tid] = __ldg(&bias[tid]);
        if (LAYER == 2) { s_s[tid] = g_stat[4 * DD + tid]; s_t[tid] = g_stat[5 * DD + tid]; }
    }
    __syncthreads();   // s_s/s_t must be visible before the tile conversion below

    int row0 = blockIdx.x * 128;
    // ---- tile load/convert: thread handles row r, 64-col half ----
    {
        int r = tid >> 1, c0 = (tid & 1) * 64;
        int grow = row0 + r;
        const float* Arow = ((LAYER == 1) ? g_A : g_Y) + (size_t)grow * DD;
        const __nv_bfloat16* Wh = g_Whi[LAYER - 1] + r * DD;
        const __nv_bfloat16* Wl = g_Wlo[LAYER - 1] + r * DD;
        char* psm = dynsm;
#pragma unroll 4
        for (int cc = 0; cc < 64; cc += 4) {
            int c = c0 + cc;
            float4 v = make_float4(0.f, 0.f, 0.f, 0.f);
            if (grow < Nn) v = *reinterpret_cast<const float4*>(Arow + c);
            if (LAYER == 2) {
                v.x = fmaxf(fmaf(v.x, s_s[c + 0], s_t[c + 0]), 0.f);
                v.y = fmaxf(fmaf(v.y, s_s[c + 1], s_t[c + 1]), 0.f);
                v.z = fmaxf(fmaf(v.z, s_s[c + 2], s_t[c + 2]), 0.f);
                v.w = fmaxf(fmaf(v.w, s_s[c + 3], s_t[c + 3]), 0.f);
            }
            __nv_bfloat162 h0 = __floats2bfloat162_rn(v.x, v.y);
            __nv_bfloat162 h1 = __floats2bfloat162_rn(v.z, v.w);
            __nv_bfloat162 l0 = __floats2bfloat162_rn(v.x - __low2float(h0), v.y - __high2float(h0));
            __nv_bfloat162 l1 = __floats2bfloat162_rn(v.z - __low2float(h1), v.w - __high2float(h1));
            uint32_t off = (uint32_t)(r * LDA + c) * 2;
            *reinterpret_cast<uint2*>(psm + off) =
                make_uint2(reinterpret_cast<uint32_t&>(h0), reinterpret_cast<uint32_t&>(h1));
            *reinterpret_cast<uint2*>(psm + 34816 + off) =
                make_uint2(reinterpret_cast<uint32_t&>(l0), reinterpret_cast<uint32_t&>(l1));
            *reinterpret_cast<uint2*>(psm + 69632 + off) = *reinterpret_cast<const uint2*>(Wh + c);
            *reinterpret_cast<uint2*>(psm + 104448 + off) = *reinterpret_cast<const uint2*>(Wl + c);
        }
    }
    __syncthreads();

    // ---- mma mainloop ----
    int warp_m = wid & 3, warp_n = wid >> 2;          // 4 x 2 warp grid
    int aRow = warp_m * 32 + (lane & 15);             // + mt*16
    int aKh  = (lane >> 4) * 8;
    int bRow = warp_n * 64 + (lane & 7) + ((lane >> 4) & 1) * 8;  // + ntp*16
    int bKh  = ((lane >> 3) & 1) * 8;

    float acc[2][8][4];
#pragma unroll
    for (int mt = 0; mt < 2; mt++)
#pragma unroll
        for (int nt = 0; nt < 8; nt++)
#pragma unroll
            for (int q = 0; q < 4; q++) acc[mt][nt][q] = 0.f;

    // pass A: A_hi x (W_hi + W_lo)
#pragma unroll
    for (int kk = 0; kk < 8; kk++) {
        int k0 = kk * 16;
        uint32_t a[2][4];
#pragma unroll
        for (int mt = 0; mt < 2; mt++)
            ldx4(a[mt], AHI + (uint32_t)((aRow + mt * 16) * LDA + k0 + aKh) * 2);
#pragma unroll
        for (int ntp = 0; ntp < 4; ntp++) {
            uint32_t boff = (uint32_t)((bRow + ntp * 16) * LDA + k0 + bKh) * 2;
            uint32_t bh[4], bl[4];
            ldx4(bh, WHI + boff);
            ldx4(bl, WLO + boff);
#pragma unroll
            for (int mt = 0; mt < 2; mt++) {
                mma16816(acc[mt][2 * ntp + 0], a[mt], bh[0], bh[1]);
                mma16816(acc[mt][2 * ntp + 1], a[mt], bh[2], bh[3]);
                mma16816(acc[mt][2 * ntp + 0], a[mt], bl[0], bl[1]);
                mma16816(acc[mt][2 * ntp + 1], a[mt], bl[2], bl[3]);
            }
        }
    }
    // pass B: A_lo x W_hi
#pragma unroll
    for (int kk = 0; kk < 8; kk++) {
        int k0 = kk * 16;
        uint32_t a[2][4];
#pragma unroll
        for (int mt = 0; mt < 2; mt++)
            ldx4(a[mt], ALO + (uint32_t)((aRow + mt * 16) * LDA + k0 + aKh) * 2);
#pragma unroll
        for (int ntp = 0; ntp < 4; ntp++) {
            uint32_t bh[4];
            ldx4(bh, WHI + (uint32_t)((bRow + ntp * 16) * LDA + k0 + bKh) * 2);
#pragma unroll
            for (int mt = 0; mt < 2; mt++) {
                mma16816(acc[mt][2 * ntp + 0], a[mt], bh[0], bh[1]);
                mma16816(acc[mt][2 * ntp + 1], a[mt], bh[2], bh[3]);
            }
        }
    }

    // ---- epilogue: bias + store ----
#pragma unroll
    for (int mt = 0; mt < 2; mt++) {
        int r0 = row0 + warp_m * 32 + mt * 16 + (lane >> 2);
        int r1 = r0 + 8;
#pragma unroll
        for (int nt = 0; nt < 8; nt++) {
            int c = warp_n * 64 + nt * 8 + (lane & 3) * 2;
            float bx = s_bias[c], by = s_bias[c + 1];
            if (r0 < Nn)
                *reinterpret_cast<float2*>(&g_Y[(size_t)r0 * DD + c]) =
                    make_float2(acc[mt][nt][0] + bx, acc[mt][nt][1] + by);
            if (r1 < Nn)
                *reinterpret_cast<float2*>(&g_Y[(size_t)r1 * DD + c]) =
                    make_float2(acc[mt][nt][2] + bx, acc[mt][nt][3] + by);
        }
    }
}

// ---------------------------------------------------------------------------
// Column sum / sum-of-squares over g_Y -> g_stat (atomics; zeroed in k_init)
template <int LAYER>
__global__ __launch_bounds__(256) void k_stats(int Nn) {
    __shared__ float s_sum[DD], s_sq[DD];
    int tid = threadIdx.x;
    if (tid < DD) { s_sum[tid] = 0.f; s_sq[tid] = 0.f; }
    __syncthreads();
    int lane = tid & 31, w = tid >> 5;
    const float4* Y4 = reinterpret_cast<const float4*>(g_Y);
    float a0 = 0, a1 = 0, a2 = 0, a3 = 0, q0 = 0, q1 = 0, q2 = 0, q3 = 0;
    for (int rr = blockIdx.x * 8 + w; rr < Nn; rr += gridDim.x * 8) {
        float4 v = Y4[(size_t)rr * 32 + lane];
        a0 += v.x; q0 = fmaf(v.x, v.x, q0);
        a1 += v.y; q1 = fmaf(v.y, v.y, q1);
        a2 += v.z; q2 = fmaf(v.z, v.z, q2);
        a3 += v.w; q3 = fmaf(v.w, v.w, q3);
    }
    int c = lane * 4;
    atomicAdd(&s_sum[c + 0], a0); atomicAdd(&s_sum[c + 1], a1);
    atomicAdd(&s_sum[c + 2], a2); atomicAdd(&s_sum[c + 3], a3);
    atomicAdd(&s_sq[c + 0], q0);  atomicAdd(&s_sq[c + 1], q1);
    atomicAdd(&s_sq[c + 2], q2);  atomicAdd(&s_sq[c + 3], q3);
    __syncthreads();
    if (tid < DD) {
        float* osum = g_stat + (LAYER == 1 ? 0 : 2 * DD);
        atomicAdd(&osum[tid], s_sum[tid]);
        atomicAdd(&osum[DD + tid], s_sq[tid]);
    }
}

// ---------------------------------------------------------------------------
template <int LAYER>
__global__ void k_bn(const float* __restrict__ g, const float* __restrict__ beta, int N) {
    int j = threadIdx.x;
    const float* sum = g_stat + (LAYER == 1 ? 0 : 2 * DD);
    float invN = 1.0f / (float)N;
    float mean = sum[j] * invN;
    float var  = sum[DD + j] * invN - mean * mean;
    float sc = __ldg(&g[j]) * rsqrtf(var + 1e-5f);
    float* outS = g_stat + (LAYER == 1 ? 4 * DD : 6 * DD);
    outS[j] = sc;
    outS[DD + j] = __ldg(&beta[j]) - mean * sc;
}

// ---------------------------------------------------------------------------
__global__ void k_final(float* __restrict__ out, int n4) {
    const float4* Y4 = reinterpret_cast<const float4*>(g_Y);
    float4* o4 = reinterpret_cast<float4*>(out);
    for (int i = blockIdx.x * blockDim.x + threadIdx.x; i < n4; i += gridDim.x * blockDim.x) {
        int cb = (i & 31) * 4;
        float4 y = Y4[i];
        float4 r;
        r.x = fmaxf(fmaf(y.x, g_stat[6 * DD + cb + 0], g_stat[7 * DD + cb + 0]), 0.f);
        r.y = fmaxf(fmaf(y.y, g_stat[6 * DD + cb + 1], g_stat[7 * DD + cb + 1]), 0.f);
        r.z = fmaxf(fmaf(y.z, g_stat[6 * DD + cb + 2], g_stat[7 * DD + cb + 2]), 0.f);
        r.w = fmaxf(fmaf(y.w, g_stat[6 * DD + cb + 3], g_stat[7 * DD + cb + 3]), 0.f);
        o4[i] = r;
    }
}

// ---------------------------------------------------------------------------
extern "C" void kernel_launch(void* const* d_in, const int* in_sizes, int n_in,
                              void* d_out, int out_size) {
    const float* x   = (const float*)d_in[0];
    const int*   ei  = (const int*)d_in[1];
    const float* eps = (const float*)d_in[2];
    const float* W1  = (const float*)d_in[3];
    const float* b1  = (const float*)d_in[4];
    const float* g1  = (const float*)d_in[5];
    const float* be1 = (const float*)d_in[6];
    const float* W2  = (const float*)d_in[7];
    const float* b2  = (const float*)d_in[8];
    const float* g2  = (const float*)d_in[9];
    const float* be2 = (const float*)d_in[10];

    int N  = in_sizes[0] / DD;
    int E  = in_sizes[1] / 2;
    int n4 = N * (DD / 4);
    int gb = (N + 127) / 128;

    const int DYN = 4 * 128 * LDA * 2;   // 139264 B
    cudaFuncSetAttribute((const void*)k_gemm_tc<1>, cudaFuncAttributeMaxDynamicSharedMemorySize, DYN);
    cudaFuncSetAttribute((const void*)k_gemm_tc<2>, cudaFuncAttributeMaxDynamicSharedMemorySize, DYN);

    k_detect<<<1, 256>>>(ei, E);
    k_init<<<2048, 256>>>((const float4*)x, eps, n4);
    k_prep<<<128, 256>>>(W1, W2);
    k_scatter<<<(E + 7) / 8, 256>>>((const float4*)x, ei, E);
    k_gemm_tc<1><<<gb, 256, DYN>>>(b1, N);
    k_stats<1><<<1184, 256>>>(N);
    k_bn<1><<<1, DD>>>(g1, be1, N);
    k_gemm_tc<2><<<gb, 256, DYN>>>(b2, N);
    k_stats<2><<<1184, 256>>>(N);
    k_bn<2><<<1, DD>>>(g2, be2, N);
    k_final<<<2048, 256>>>((float*)d_out, n4);
}

// round 7
// speedup vs baseline: 3.8697x; 1.0978x over previous
#include <cuda_runtime.h>
#include <cuda_bf16.h>
#include <cstdint>

#define DD 128
#define MAXN 100000
#define MAXE 655360
#define LDA 136                      // smem tile stride (bf16 elems), conflict-free ldmatrix

// ---- scratch (no allocs allowed) -------------------------------------------
__device__ __align__(16) float g_A[(size_t)MAXN * DD];   // (1+eps)x + aggr
__device__ __align__(16) float g_Y[(size_t)MAXN * DD];   // layer outputs (in-place L2)
// [0:128) sum1 [128:256) sq1 [256:384) sum2 [384:512) sq2
// [512:640) s1 [640:768) t1 [768:896) s2 [896:1024) t2
__device__ float g_stat[8 * DD];
__device__ int   g_i64flag;
__device__ __align__(16) __nv_bfloat16 g_Whi[2][DD * DD];
__device__ __align__(16) __nv_bfloat16 g_Wlo[2][DD * DD];
// CSR scratch
__device__ int g_cnt[MAXN + 1];
__device__ int g_off[MAXN + 1];
__device__ int g_cur[MAXN];
__device__ int g_srcid[MAXE];
__device__ int g_blksum[256];
__device__ int g_blkoff[256];

#define SMEMU32(p) ((uint32_t)__cvta_generic_to_shared(p))

__device__ __forceinline__ void ldx4(uint32_t* r, uint32_t addr) {
    asm volatile("ldmatrix.sync.aligned.m8n8.x4.shared.b16 {%0,%1,%2,%3}, [%4];"
                 : "=r"(r[0]), "=r"(r[1]), "=r"(r[2]), "=r"(r[3]) : "r"(addr));
}
__device__ __forceinline__ void mma16816(float* c, const uint32_t* a, uint32_t b0, uint32_t b1) {
    asm volatile("mma.sync.aligned.m16n8k16.row.col.f32.bf16.bf16.f32 "
                 "{%0,%1,%2,%3}, {%4,%5,%6,%7}, {%8,%9}, {%0,%1,%2,%3};"
                 : "+f"(c[0]), "+f"(c[1]), "+f"(c[2]), "+f"(c[3])
                 : "r"(a[0]), "r"(a[1]), "r"(a[2]), "r"(a[3]), "r"(b0), "r"(b1));
}

// ---------------------------------------------------------------------------
__global__ void k_detect(const int* __restrict__ w, int E) {
    __shared__ int s_or;
    if (threadIdx.x == 0) s_or = 0;
    __syncthreads();
    int total = 2 * E;
    int step = total / 4096; if (step < 2) step = 2;
    int acc = 0;
    for (int i = threadIdx.x; i < 4096; i += blockDim.x) {
        long long idx = ((long long)i * step) | 1;
        if (idx < total) acc |= w[idx];
    }
    atomicOr(&s_or, acc);
    __syncthreads();
    if (threadIdx.x == 0) g_i64flag = (s_or == 0) ? 1 : 0;
}

// ---------------------------------------------------------------------------
// zero degree counters + BN stat accumulators
__global__ void k_zero(int Nn) {
    if (blockIdx.x == 0 && threadIdx.x < 256) {
        g_stat[threadIdx.x] = 0.0f;
        g_stat[threadIdx.x + 256] = 0.0f;
    }
    for (int i = blockIdx.x * blockDim.x + threadIdx.x; i < Nn; i += gridDim.x * blockDim.x)
        g_cnt[i] = 0;
}

// ---------------------------------------------------------------------------
__global__ void k_hist(const int* __restrict__ w, int E) {
    int e = blockIdx.x * blockDim.x + threadIdx.x;
    if (e >= E) return;
    int d = g_i64flag ? __ldg(&w[2 * (E + e)]) : __ldg(&w[E + e]);
    atomicAdd(&g_cnt[d], 1);
}

// ---- 3-stage exclusive scan of g_cnt -> g_off (chunk = 512 per block) ------
__global__ void k_scanA(int Nn) {
    __shared__ int sm[256];
    int b = blockIdx.x, t = threadIdx.x;
    int base = b * 512;
    int v = 0;
    if (base + t < Nn)       v += g_cnt[base + t];
    if (base + t + 256 < Nn) v += g_cnt[base + t + 256];
    sm[t] = v; __syncthreads();
    for (int o = 128; o > 0; o >>= 1) { if (t < o) sm[t] += sm[t + o]; __syncthreads(); }
    if (t == 0) g_blksum[b] = sm[0];
}
__global__ void k_scanB(int nblk) {
    __shared__ int sm[256];
    int t = threadIdx.x;
    int v = (t < nblk) ? g_blksum[t] : 0;
    sm[t] = v; __syncthreads();
    for (int o = 1; o < 256; o <<= 1) {
        int a = (t >= o) ? sm[t - o] : 0;
        __syncthreads(); sm[t] += a; __syncthreads();
    }
    if (t < nblk) g_blkoff[t] = sm[t] - v;   // exclusive
}
__global__ void k_scanC(int Nn) {
    __shared__ int sm[256];
    int b = blockIdx.x, t = threadIdx.x;
    int i0 = b * 512 + 2 * t, i1 = i0 + 1;
    int c0 = (i0 < Nn) ? g_cnt[i0] : 0;
    int c1 = (i1 < Nn) ? g_cnt[i1] : 0;
    int v = c0 + c1;
    sm[t] = v; __syncthreads();
    for (int o = 1; o < 256; o <<= 1) {
        int a = (t >= o) ? sm[t - o] : 0;
        __syncthreads(); sm[t] += a; __syncthreads();
    }
    int excl = sm[t] - v + g_blkoff[b];
    if (i0 < Nn) { g_off[i0] = excl;      g_cur[i0] = excl; }
    if (i1 < Nn) { g_off[i1] = excl + c0; g_cur[i1] = excl + c0; }
}

// ---------------------------------------------------------------------------
__global__ void k_fill(const int* __restrict__ w, int E) {
    int e = blockIdx.x * blockDim.x + threadIdx.x;
    if (e >= E) return;
    int s, d;
    if (g_i64flag) { s = __ldg(&w[2 * e]); d = __ldg(&w[2 * (E + e)]); }
    else           { s = __ldg(&w[e]);     d = __ldg(&w[E + e]); }
    int p = atomicAdd(&g_cur[d], 1);
    g_srcid[p] = s;
}

// ---------------------------------------------------------------------------
// One warp per node: A[d] = (1+eps)*x[d] + sum_{e in bucket(d)} x[src(e)]
__global__ __launch_bounds__(256) void k_aggr(const float4* __restrict__ x,
                                              const float* __restrict__ eps, int Nn, int E) {
    int gw = (blockIdx.x * blockDim.x + threadIdx.x) >> 5;
    int lane = threadIdx.x & 31;
    if (gw >= Nn) return;
    float e = 1.0f + __ldg(eps);
    int beg = g_off[gw];
    int end = (gw + 1 < Nn) ? g_off[gw + 1] : E;
    float4 a = __ldg(&x[(size_t)gw * 32 + lane]);
    float4 acc = make_float4(a.x * e, a.y * e, a.z * e, a.w * e);
    int i = beg;
    for (; i + 3 < end; i += 4) {
        int s0 = __ldg(&g_srcid[i + 0]), s1 = __ldg(&g_srcid[i + 1]);
        int s2 = __ldg(&g_srcid[i + 2]), s3 = __ldg(&g_srcid[i + 3]);
        float4 v0 = __ldg(&x[(size_t)s0 * 32 + lane]);
        float4 v1 = __ldg(&x[(size_t)s1 * 32 + lane]);
        float4 v2 = __ldg(&x[(size_t)s2 * 32 + lane]);
        float4 v3 = __ldg(&x[(size_t)s3 * 32 + lane]);
        acc.x += v0.x + v1.x + v2.x + v3.x;
        acc.y += v0.y + v1.y + v2.y + v3.y;
        acc.z += v0.z + v1.z + v2.z + v3.z;
        acc.w += v0.w + v1.w + v2.w + v3.w;
    }
    for (; i < end; i++) {
        int s = __ldg(&g_srcid[i]);
        float4 v = __ldg(&x[(size_t)s * 32 + lane]);
        acc.x += v.x; acc.y += v.y; acc.z += v.z; acc.w += v.w;
    }
    *reinterpret_cast<float4*>(&g_A[(size_t)gw * DD + lane * 4]) = acc;
}

// ---------------------------------------------------------------------------
__global__ void k_prep(const float* __restrict__ W1, const float* __restrict__ W2) {
    int i = blockIdx.x * blockDim.x + threadIdx.x;
    if (i >= 2 * DD * DD) return;
    int layer = i >> 14, j = i & (DD * DD - 1);
    float v = (layer == 0) ? W1[j] : W2[j];
    __nv_bfloat16 h = __float2bfloat16_rn(v);
    g_Whi[layer][j] = h;
    g_Wlo[layer][j] = __float2bfloat16_rn(v - __bfloat162float(h));
}

// ---------------------------------------------------------------------------
// mma.sync GEMM: CTA = 128x128 tile, K=128. bf16 hi/lo x3 emulation.
// Fused epilogue: bias + store + per-column BN sum/sumsq accumulation.
// smem: A_hi @0, A_lo @34816, W_hi @69632, W_lo @104448 (128 x LDA bf16 each)
template <int LAYER>
__global__ __launch_bounds__(256) void k_gemm_tc(const float* __restrict__ bias, int Nn) {
    extern __shared__ char dynsm[];
    __shared__ float s_bias[DD];
    __shared__ float s_s[DD], s_t[DD];
    __shared__ float s_sum[DD], s_sq[DD];

    const uint32_t sbase = SMEMU32(dynsm);
    const uint32_t AHI = sbase, ALO = sbase + 34816, WHI = sbase + 69632, WLO = sbase + 104448;

    int tid = threadIdx.x, wid = tid >> 5, lane = tid & 31;
    if (tid < DD) {
        s_bias[tid] = __ldg(&bias[tid]);
        s_sum[tid] = 0.f; s_sq[tid] = 0.f;
        if (LAYER == 2) { s_s[tid] = g_stat[4 * DD + tid]; s_t[tid] = g_stat[5 * DD + tid]; }
    }
    __syncthreads();   // s_s/s_t/s_sum visible before use

    int row0 = blockIdx.x * 128;
    // ---- tile load/convert: thread handles row r, 64-col half ----
    {
        int r = tid >> 1, c0 = (tid & 1) * 64;
        int grow = row0 + r;
        const float* Arow = ((LAYER == 1) ? g_A : g_Y) + (size_t)grow * DD;
        const __nv_bfloat16* Wh = g_Whi[LAYER - 1] + r * DD;
        const __nv_bfloat16* Wl = g_Wlo[LAYER - 1] + r * DD;
        char* psm = dynsm;
#pragma unroll 4
        for (int cc = 0; cc < 64; cc += 4) {
            int c = c0 + cc;
            float4 v = make_float4(0.f, 0.f, 0.f, 0.f);
            if (grow < Nn) v = *reinterpret_cast<const float4*>(Arow + c);
            if (LAYER == 2) {
                v.x = fmaxf(fmaf(v.x, s_s[c + 0], s_t[c + 0]), 0.f);
                v.y = fmaxf(fmaf(v.y, s_s[c + 1], s_t[c + 1]), 0.f);
                v.z = fmaxf(fmaf(v.z, s_s[c + 2], s_t[c + 2]), 0.f);
                v.w = fmaxf(fmaf(v.w, s_s[c + 3], s_t[c + 3]), 0.f);
            }
            __nv_bfloat162 h0 = __floats2bfloat162_rn(v.x, v.y);
            __nv_bfloat162 h1 = __floats2bfloat162_rn(v.z, v.w);
            __nv_bfloat162 l0 = __floats2bfloat162_rn(v.x - __low2float(h0), v.y - __high2float(h0));
            __nv_bfloat162 l1 = __floats2bfloat162_rn(v.z - __low2float(h1), v.w - __high2float(h1));
            uint32_t off = (uint32_t)(r * LDA + c) * 2;
            *reinterpret_cast<uint2*>(psm + off) =
                make_uint2(reinterpret_cast<uint32_t&>(h0), reinterpret_cast<uint32_t&>(h1));
            *reinterpret_cast<uint2*>(psm + 34816 + off) =
                make_uint2(reinterpret_cast<uint32_t&>(l0), reinterpret_cast<uint32_t&>(l1));
            *reinterpret_cast<uint2*>(psm + 69632 + off) = *reinterpret_cast<const uint2*>(Wh + c);
            *reinterpret_cast<uint2*>(psm + 104448 + off) = *reinterpret_cast<const uint2*>(Wl + c);
        }
    }
    __syncthreads();

    // ---- merged mma mainloop: D = Ah*Wh + Ah*Wl + Al*Wh ----
    int warp_m = wid & 3, warp_n = wid >> 2;          // 4 x 2 warp grid
    int aRow = warp_m * 32 + (lane & 15);
    int aKh  = (lane >> 4) * 8;
    int bRow = warp_n * 64 + (lane & 7) + ((lane >> 4) & 1) * 8;
    int bKh  = ((lane >> 3) & 1) * 8;

    float acc[2][8][4];
#pragma unroll
    for (int mt = 0; mt < 2; mt++)
#pragma unroll
        for (int nt = 0; nt < 8; nt++)
#pragma unroll
            for (int q = 0; q < 4; q++) acc[mt][nt][q] = 0.f;

#pragma unroll
    for (int kk = 0; kk < 8; kk++) {
        int k0 = kk * 16;
        uint32_t ah[2][4], al[2][4];
#pragma unroll
        for (int mt = 0; mt < 2; mt++) {
            uint32_t aoff = (uint32_t)((aRow + mt * 16) * LDA + k0 + aKh) * 2;
            ldx4(ah[mt], AHI + aoff);
            ldx4(al[mt], ALO + aoff);
        }
#pragma unroll
        for (int ntp = 0; ntp < 4; ntp++) {
            uint32_t boff = (uint32_t)((bRow + ntp * 16) * LDA + k0 + bKh) * 2;
            uint32_t bh[4], bl[4];
            ldx4(bh, WHI + boff);
            ldx4(bl, WLO + boff);
#pragma unroll
            for (int mt = 0; mt < 2; mt++) {
                mma16816(acc[mt][2 * ntp + 0], ah[mt], bh[0], bh[1]);
                mma16816(acc[mt][2 * ntp + 1], ah[mt], bh[2], bh[3]);
                mma16816(acc[mt][2 * ntp + 0], ah[mt], bl[0], bl[1]);
                mma16816(acc[mt][2 * ntp + 1], ah[mt], bl[2], bl[3]);
                mma16816(acc[mt][2 * ntp + 0], al[mt], bh[0], bh[1]);
                mma16816(acc[mt][2 * ntp + 1], al[mt], bh[2], bh[3]);
            }
        }
    }

    // ---- epilogue: bias + store + fused BN stats ----
#pragma unroll
    for (int mt = 0; mt < 2; mt++) {
        int r0 = row0 + warp_m * 32 + mt * 16 + (lane >> 2);
        int r1 = r0 + 8;
#pragma unroll
        for (int nt = 0; nt < 8; nt++) {
            int c = warp_n * 64 + nt * 8 + (lane & 3) * 2;
            float bx = s_bias[c], by = s_bias[c + 1];
            float v00 = acc[mt][nt][0] + bx, v01 = acc[mt][nt][1] + by;
            float v10 = acc[mt][nt][2] + bx, v11 = acc[mt][nt][3] + by;
            float cs0 = 0.f, cs1 = 0.f, cq0 = 0.f, cq1 = 0.f;
            if (r0 < Nn) {
                *reinterpret_cast<float2*>(&g_Y[(size_t)r0 * DD + c]) = make_float2(v00, v01);
                cs0 += v00; cs1 += v01;
                cq0 = fmaf(v00, v00, cq0); cq1 = fmaf(v01, v01, cq1);
            }
            if (r1 < Nn) {
                *reinterpret_cast<float2*>(&g_Y[(size_t)r1 * DD + c]) = make_float2(v10, v11);
                cs0 += v10; cs1 += v11;
                cq0 = fmaf(v10, v10, cq0); cq1 = fmaf(v11, v11, cq1);
            }
            // reduce over the 8 lanes sharing this column pair (lane ^ {4,8,16})
#pragma unroll
            for (int m = 4; m <= 16; m <<= 1) {
                cs0 += __shfl_xor_sync(0xffffffffu, cs0, m);
                cs1 += __shfl_xor_sync(0xffffffffu, cs1, m);
                cq0 += __shfl_xor_sync(0xffffffffu, cq0, m);
                cq1 += __shfl_xor_sync(0xffffffffu, cq1, m);
            }
            if ((lane >> 2) == 0) {
                atomicAdd(&s_sum[c], cs0);     atomicAdd(&s_sum[c + 1], cs1);
                atomicAdd(&s_sq[c], cq0);      atomicAdd(&s_sq[c + 1], cq1);
            }
        }
    }
    __syncthreads();
    if (tid < DD) {
        float* osum = g_stat + (LAYER == 1 ? 0 : 2 * DD);
        atomicAdd(&osum[tid], s_sum[tid]);
        atomicAdd(&osum[DD + tid], s_sq[tid]);
    }
}

// ---------------------------------------------------------------------------
template <int LAYER>
__global__ void k_bn(const float* __restrict__ g, const float* __restrict__ beta, int N) {
    int j = threadIdx.x;
    const float* sum = g_stat + (LAYER == 1 ? 0 : 2 * DD);
    float invN = 1.0f / (float)N;
    float mean = sum[j] * invN;
    float var  = sum[DD + j] * invN - mean * mean;
    float sc = __ldg(&g[j]) * rsqrtf(var + 1e-5f);
    float* outS = g_stat + (LAYER == 1 ? 4 * DD : 6 * DD);
    outS[j] = sc;
    outS[DD + j] = __ldg(&beta[j]) - mean * sc;
}

// ---------------------------------------------------------------------------
__global__ void k_final(float* __restrict__ out, int n4) {
    const float4* Y4 = reinterpret_cast<const float4*>(g_Y);
    float4* o4 = reinterpret_cast<float4*>(out);
    for (int i = blockIdx.x * blockDim.x + threadIdx.x; i < n4; i += gridDim.x * blockDim.x) {
        int cb = (i & 31) * 4;
        float4 y = Y4[i];
        float4 r;
        r.x = fmaxf(fmaf(y.x, g_stat[6 * DD + cb + 0], g_stat[7 * DD + cb + 0]), 0.f);
        r.y = fmaxf(fmaf(y.y, g_stat[6 * DD + cb + 1], g_stat[7 * DD + cb + 1]), 0.f);
        r.z = fmaxf(fmaf(y.z, g_stat[6 * DD + cb + 2], g_stat[7 * DD + cb + 2]), 0.f);
        r.w = fmaxf(fmaf(y.w, g_stat[6 * DD + cb + 3], g_stat[7 * DD + cb + 3]), 0.f);
        o4[i] = r;
    }
}

// ---------------------------------------------------------------------------
extern "C" void kernel_launch(void* const* d_in, const int* in_sizes, int n_in,
                              void* d_out, int out_size) {
    const float* x   = (const float*)d_in[0];
    const int*   ei  = (const int*)d_in[1];
    const float* eps = (const float*)d_in[2];
    const float* W1  = (const float*)d_in[3];
    const float* b1  = (const float*)d_in[4];
    const float* g1  = (const float*)d_in[5];
    const float* be1 = (const float*)d_in[6];
    const float* W2  = (const float*)d_in[7];
    const float* b2  = (const float*)d_in[8];
    const float* g2  = (const float*)d_in[9];
    const float* be2 = (const float*)d_in[10];

    int N  = in_sizes[0] / DD;
    int E  = in_sizes[1] / 2;
    int n4 = N * (DD / 4);
    int gb = (N + 127) / 128;
    int nblk = (N + 511) / 512;          // scan blocks (<=256 for N<=131072)
    int eb = (E + 255) / 256;

    const int DYN = 4 * 128 * LDA * 2;   // 139264 B
    cudaFuncSetAttribute((const void*)k_gemm_tc<1>, cudaFuncAttributeMaxDynamicSharedMemorySize, DYN);
    cudaFuncSetAttribute((const void*)k_gemm_tc<2>, cudaFuncAttributeMaxDynamicSharedMemorySize, DYN);

    k_detect<<<1, 256>>>(ei, E);
    k_zero<<<400, 256>>>(N);
    k_prep<<<128, 256>>>(W1, W2);
    k_hist<<<eb, 256>>>(ei, E);
    k_scanA<<<nblk, 256>>>(N);
    k_scanB<<<1, 256>>>(nblk);
    k_scanC<<<nblk, 256>>>(N);
    k_fill<<<eb, 256>>>(ei, E);
    k_aggr<<<(N * 32 + 255) / 256, 256>>>((const float4*)x, eps, N, E);
    k_gemm_tc<1><<<gb, 256, DYN>>>(b1, N);
    k_bn<1><<<1, DD>>>(g1, be1, N);
    k_gemm_tc<2><<<gb, 256, DYN>>>(b2, N);
    k_bn<2><<<1, DD>>>(g2, be2, N);
    k_final<<<2048, 256>>>((float*)d_out, n4);
}